// round 15
// baseline (speedup 1.0000x reference)
#include <cuda_runtime.h>
#include <math.h>

#define BB 32
#define PP 64
#define LL 64
#define VV 32000
#define NROW (BB * PP)       // 2048

// Scratch (no allocations allowed). Zero-initialized at module load.
// g_flag / g_done are reset by the last block each run (graph-replay safe).
__device__ uint2    g_mask[NROW];    // truth bitmask per (b,i)
__device__ int      g_flag[BB];      // DP-done flag per batch
__device__ float    g_sum[NROW];     // per-row sum over V
__device__ float    g_S[NROW];       // per-row sum at distinct argmins
__device__ int      g_m[NROW];       // per-row distinct argmin count
__device__ unsigned g_done;          // block completion counter

// ---------------------------------------------------------------------------
// Single kernel, grid = 2048 x 256, one row per block (measured-best shape).
// R13 delta vs R12: stream loop is explicitly software-pipelined — batches of
// 4 back-to-back __ldcs loads land in independent registers while the
// previous batch's adds retire (guaranteed ~8 LDG.128 in flight per warp,
// independent of ptxas scheduling). Outer loop not unrolled (keeps regs low).
// Order: (DP blocks 0..31) -> stream own row -> flag-wait (DP hidden) ->
// dedup-gather epilogue -> last-block fp32 log1p finisher.
//
// Analytic collapse: q has 2 levels -> p1=e/D, p0=1/D, D=(V-m)+m*e.
// lnD = ln(V) + log1p(m*(e-1)/V);  kl = m*p1*(1-lnD) - (V-m)*p0*lnD
//                                      - p0*sumAll - (p1-p0)*Ssum
// ---------------------------------------------------------------------------
__global__ void __launch_bounds__(256, 8)
k_main(const float* __restrict__ outputs,
       const int* __restrict__ syms,
       const int* __restrict__ targets,
       const unsigned char* __restrict__ mask,
       float* __restrict__ out) {
    const unsigned FULL = 0xffffffffu;
    int bp   = blockIdx.x;            // 0..2047 (row id)
    int b    = bp >> 6;
    int tid  = threadIdx.x;
    int lane = tid & 31, wid = tid >> 5;

    // ---------------- DP (blocks 0..31, warp 0 only) ----------------
    if (bp < BB && wid == 0) {
        int bd = bp;
        int j0 = 2 * lane, j1 = 2 * lane + 1;
        int tg0 = targets[bd * LL + j0];
        int tg1 = targets[bd * LL + j1];
        int mk0 = mask[bd * LL + j0];
        int mk1 = mask[bd * LL + j1];
        int s0  = syms[bd * PP + j0];
        int s1  = syms[bd * PP + j1];
        int tgm1 = __shfl_up_sync(FULL, tg1, 1);   // tg[j0-1]
        float p0 = (float)j0, p1 = (float)j1;      // row 0 (exact ints in fp32)

        for (int i = 0; i < PP; i++) {
            float d0, d1;
            if (i == 0) {
                d0 = p0; d1 = p1;
            } else {
                int im1 = i - 1;
                int sym = __shfl_sync(FULL, (im1 & 1) ? s1 : s0, im1 >> 1);
                float p1m = __shfl_up_sync(FULL, p1, 1);    // prev[j0-1]
                float tmp0 = (lane == 0) ? (float)i
                           : fminf(p1m + ((sym != tgm1) ? 1.0f : 0.0f), p0 + 1.0f);
                float tmp1 = fminf(p0 + ((sym != tg0) ? 1.0f : 0.0f), p1 + 1.0f);
                float v0 = tmp0 - (float)j0;
                float sB = fminf(v0, tmp1 - (float)j1);     // pair-inclusive
                float sc = sB;
                #pragma unroll
                for (int off = 1; off < 32; off <<= 1) {
                    float o = __shfl_up_sync(FULL, sc, off);
                    if (lane >= off) sc = fminf(sc, o);
                }
                float e = __shfl_up_sync(FULL, sc, 1);      // exclusive prefix
                if (lane == 0) e = INFINITY;
                d0 = (float)j0 + fminf(e, v0);
                d1 = (float)j1 + fminf(e, sB);
                p0 = d0; p1 = d1;
            }
            float md0 = mk0 ? d0 : INFINITY;
            float md1 = mk1 ? d1 : INFINITY;
            float mv = fminf(md0, md1);
            #pragma unroll
            for (int off = 16; off; off >>= 1)
                mv = fminf(mv, __shfl_xor_sync(FULL, mv, off));
            unsigned mE = __ballot_sync(FULL, md0 == mv);
            unsigned mO = __ballot_sync(FULL, md1 == mv);
            if (lane == 0) g_mask[bd * PP + i] = make_uint2(mE, mO);
        }
        __threadfence();
        if (lane == 0) atomicExch(&g_flag[bd], 1);
    }

    // -------- rowsum: software-pipelined batches of 4 LDG.128 --------
    // Thread t covers idx = t + 256k, k = 0..30 (7936) + tail (64).
    // Pipeline: load batch B(n+1) while summing batch B(n). ~8 loads in flight.
    const float4* row4 = (const float4*)(outputs + (size_t)bp * VV);
    float a0 = 0.0f, a1 = 0.0f, a2 = 0.0f, a3 = 0.0f;
    {
        const float4* p = row4 + tid;
        float4 v0, v1, v2, v3, w0, w1, w2, w3;
        // prologue: batch 0 (k=0..3)
        v0 = __ldcs(p);          v1 = __ldcs(p + 256);
        v2 = __ldcs(p + 512);    v3 = __ldcs(p + 768);
        p += 1024;
        #pragma unroll 1
        for (int it = 0; it < 6; it++, p += 1024) {     // batches 1..6 (k=4..27)
            w0 = __ldcs(p);          w1 = __ldcs(p + 256);
            w2 = __ldcs(p + 512);    w3 = __ldcs(p + 768);
            a0 += (v0.x + v0.y) + (v0.z + v0.w);
            a1 += (v1.x + v1.y) + (v1.z + v1.w);
            a2 += (v2.x + v2.y) + (v2.z + v2.w);
            a3 += (v3.x + v3.y) + (v3.z + v3.w);
            v0 = w0; v1 = w1; v2 = w2; v3 = w3;
        }
        // k=28,29,30 + tail(64) issued while draining batch 6
        w0 = __ldcs(p);          w1 = __ldcs(p + 256);
        w2 = __ldcs(p + 512);
        a0 += (v0.x + v0.y) + (v0.z + v0.w);
        a1 += (v1.x + v1.y) + (v1.z + v1.w);
        a2 += (v2.x + v2.y) + (v2.z + v2.w);
        a3 += (v3.x + v3.y) + (v3.z + v3.w);
        if (tid < (VV / 4 - 7936)) {                    // tail: 64 float4
            float4 t4 = __ldcs(row4 + 7936 + tid);
            a3 += (t4.x + t4.y) + (t4.z + t4.w);
        }
        a0 += (w0.x + w0.y) + (w0.z + w0.w);
        a1 += (w1.x + w1.y) + (w1.z + w1.w);
        a2 += (w2.x + w2.y) + (w2.z + w2.w);
    }
    float acc = (a0 + a1) + (a2 + a3);
    #pragma unroll
    for (int off = 16; off; off >>= 1)
        acc += __shfl_down_sync(FULL, acc, off);
    __shared__ float sred[8];
    if (lane == 0) sred[wid] = acc;

    // ---------------- wait for this batch's DP mask (hidden) --------
    if (tid == 0) {
        while (atomicAdd(&g_flag[b], 0) == 0) __nanosleep(64);
    }
    __syncthreads();
    __threadfence();

    // ---------------- dedup gather of distinct argmin symbols ------
    __shared__ int stg[LL];
    __shared__ unsigned char str[LL];
    if (tid < LL) {
        stg[tid] = targets[b * LL + tid];
        uint2 m = g_mask[bp];
        str[tid] = (unsigned char)((((tid & 1) ? m.y : m.x) >> (tid >> 1)) & 1);
    }
    __syncthreads();

    float contrib = 0.0f, cm = 0.0f;
    if (tid < LL && str[tid]) {
        int tv = stg[tid];
        bool first = true;
        for (int k = 0; k < tid; k++)
            if (str[k] && stg[k] == tv) { first = false; break; }
        if (first) {
            contrib = outputs[(size_t)bp * VV + tv];
            cm = 1.0f;
        }
    }
    #pragma unroll
    for (int off = 16; off; off >>= 1) {
        contrib += __shfl_down_sync(FULL, contrib, off);
        cm      += __shfl_down_sync(FULL, cm, off);
    }
    __shared__ float sc2[2], sm2[2];
    if (tid < LL && lane == 0) { sc2[wid] = contrib; sm2[wid] = cm; }
    __syncthreads();

    if (tid == 0) {
        float s = 0.0f;
        #pragma unroll
        for (int w = 0; w < 8; w++) s += sred[w];
        g_sum[bp] = s;
        g_S[bp]   = sc2[0] + sc2[1];
        g_m[bp]   = (int)(sm2[0] + sm2[1]);
    }

    // ---------------- last-block finisher (all fp32) ----------------
    __shared__ int s_last;
    if (tid == 0) {
        __threadfence();
        unsigned prev = atomicAdd(&g_done, 1u);
        s_last = (prev == (unsigned)(gridDim.x - 1));
    }
    __syncthreads();
    if (!s_last) return;

    // thread t = bb*8 + s : batch bb, rows i = s + 8*k (k<8). Deterministic.
    const float E1f  = 2.71828182845904523f;
    const float EM1V = 1.71828182845904523f / 32000.0f;
    const float LNV  = 10.37349118f;                 // ln(32000)
    int bb = tid >> 3, sl = tid & 7;

    float kacc = 0.0f, cnt = 0.0f;
    #pragma unroll
    for (int k = 0; k < 8; k++) {
        int i = sl + 8 * k;
        int r = bb * PP + i;
        if (mask[bb * LL + i]) {
            float mm  = (float)g_m[r];
            float D   = ((float)VV - mm) + mm * E1f;
            float p0  = 1.0f / D;
            float p1  = E1f * p0;
            float x   = mm * EM1V;
            float l1p = x * (1.0f + x * (-0.5f + x * (0.33333333f + x * -0.25f)));
            float lnD = LNV + l1p;
            kacc += mm * p1 * (1.0f - lnD) - ((float)VV - mm) * p0 * lnD
                  - p0 * g_sum[r] - (p1 - p0) * g_S[r];
            cnt  += 1.0f;
        }
    }
    __shared__ float spart[256], scnt[256];
    spart[tid] = kacc; scnt[tid] = cnt;
    __syncthreads();

    if (tid < BB) {
        float s = 0.0f, w = 0.0f;
        #pragma unroll
        for (int k = 0; k < 8; k++) { s += spart[tid * 8 + k]; w += scnt[tid * 8 + k]; }
        float pb = s / (w + 1e-13f);
        float ne = (w > 0.0f) ? 1.0f : 0.0f;
        #pragma unroll
        for (int off = 16; off; off >>= 1) {
            pb += __shfl_down_sync(FULL, pb, off);
            ne += __shfl_down_sync(FULL, ne, off);
        }
        if (tid == 0) out[0] = pb / (ne + 1e-13f);
        g_flag[tid] = 0;                   // reset handshake for next replay
        if (tid == 0) g_done = 0u;
    }
}

// ---------------------------------------------------------------------------
extern "C" void kernel_launch(void* const* d_in, const int* in_sizes, int n_in,
                              void* d_out, int out_size) {
    const float*         outputs = (const float*)d_in[0];
    const int*           syms    = (const int*)d_in[1];
    const int*           targets = (const int*)d_in[2];
    const unsigned char* mask    = (const unsigned char*)d_in[3];

    k_main<<<NROW, 256>>>(outputs, syms, targets, mask, (float*)d_out);
}

// round 16
// speedup vs baseline: 1.0501x; 1.0501x over previous
#include <cuda_runtime.h>
#include <math.h>

#define BB 32
#define PP 64
#define LL 64
#define VV 32000
#define NROW (BB * PP)       // 2048
#define NBLK (NROW + BB)     // 32 DP blocks (first) + 2048 stream blocks

// Scratch (no allocations allowed). Zero-initialized at module load.
// g_flag / g_done are reset by the last block each run (graph-replay safe).
__device__ uint2    g_mask[NROW];    // truth bitmask per (b,i)
__device__ int      g_flag[BB];      // DP-done flag per batch
__device__ float    g_sum[NROW];     // per-row sum over V
__device__ float    g_S[NROW];       // per-row sum at distinct argmins
__device__ int      g_m[NROW];       // per-row distinct argmin count
__device__ unsigned g_done;          // block completion counter

// ---------------------------------------------------------------------------
// Single kernel, grid = 2080 x 256.
//   blocks 0..31   : DEDICATED DP blocks (warp 0 does the edit-distance DP,
//                    registers+shuffles only; block exits immediately after).
//                    Lowest block IDs -> guaranteed wave-1 resident -> the
//                    flag handshake cannot deadlock.
//   blocks 32..2079: pure stream blocks, one row each (R12's measured-best
//                    stream: multi-accumulator unroll-8 __ldcs loop), then
//                    flag-wait (DP long done), dedup-gather epilogue.
//   last block     : fp32 log1p-polynomial finisher, writes scalar, resets
//                    g_flag/g_done for graph replay.
//
// Analytic collapse: q has 2 levels -> p1=e/D, p0=1/D, D=(V-m)+m*e.
// lnD = ln(V) + log1p(m*(e-1)/V);  ln p1 = 1-lnD;  ln p0 = -lnD.
// kl = m*p1*(1-lnD) - (V-m)*p0*lnD - p0*sumAll - (p1-p0)*Ssum
// ---------------------------------------------------------------------------
__global__ void __launch_bounds__(256, 8)
k_main(const float* __restrict__ outputs,
       const int* __restrict__ syms,
       const int* __restrict__ targets,
       const unsigned char* __restrict__ mask,
       float* __restrict__ out) {
    const unsigned FULL = 0xffffffffu;
    int blk  = blockIdx.x;            // 0..2079
    int tid  = threadIdx.x;
    int lane = tid & 31, wid = tid >> 5;

    if (blk < BB) {
        // ================= dedicated DP block =================
        if (wid == 0) {
            int bd = blk;
            int j0 = 2 * lane, j1 = 2 * lane + 1;
            int tg0 = targets[bd * LL + j0];
            int tg1 = targets[bd * LL + j1];
            int mk0 = mask[bd * LL + j0];
            int mk1 = mask[bd * LL + j1];
            int s0  = syms[bd * PP + j0];
            int s1  = syms[bd * PP + j1];
            int tgm1 = __shfl_up_sync(FULL, tg1, 1);   // tg[j0-1]
            float p0 = (float)j0, p1 = (float)j1;      // row 0 (exact ints)

            for (int i = 0; i < PP; i++) {
                float d0, d1;
                if (i == 0) {
                    d0 = p0; d1 = p1;
                } else {
                    int im1 = i - 1;
                    int sym = __shfl_sync(FULL, (im1 & 1) ? s1 : s0, im1 >> 1);
                    float p1m = __shfl_up_sync(FULL, p1, 1);    // prev[j0-1]
                    float tmp0 = (lane == 0) ? (float)i
                               : fminf(p1m + ((sym != tgm1) ? 1.0f : 0.0f), p0 + 1.0f);
                    float tmp1 = fminf(p0 + ((sym != tg0) ? 1.0f : 0.0f), p1 + 1.0f);
                    float v0 = tmp0 - (float)j0;
                    float sB = fminf(v0, tmp1 - (float)j1);     // pair-inclusive
                    float sc = sB;
                    #pragma unroll
                    for (int off = 1; off < 32; off <<= 1) {
                        float o = __shfl_up_sync(FULL, sc, off);
                        if (lane >= off) sc = fminf(sc, o);
                    }
                    float e = __shfl_up_sync(FULL, sc, 1);      // exclusive prefix
                    if (lane == 0) e = INFINITY;
                    d0 = (float)j0 + fminf(e, v0);
                    d1 = (float)j1 + fminf(e, sB);
                    p0 = d0; p1 = d1;
                }
                float md0 = mk0 ? d0 : INFINITY;
                float md1 = mk1 ? d1 : INFINITY;
                float mv = fminf(md0, md1);
                #pragma unroll
                for (int off = 16; off; off >>= 1)
                    mv = fminf(mv, __shfl_xor_sync(FULL, mv, off));
                unsigned mE = __ballot_sync(FULL, md0 == mv);
                unsigned mO = __ballot_sync(FULL, md1 == mv);
                if (lane == 0) g_mask[bd * PP + i] = make_uint2(mE, mO);
            }
            __threadfence();
            if (lane == 0) atomicExch(&g_flag[bd], 1);
        }
        __syncthreads();
        // participate in completion counting (cannot realistically be last,
        // but the finisher below is correct regardless).
        __shared__ int s_last_dp;
        if (tid == 0) {
            __threadfence();
            unsigned prev = atomicAdd(&g_done, 1u);
            s_last_dp = (prev == (unsigned)(NBLK - 1));
        }
        __syncthreads();
        if (!s_last_dp) return;
        // fall through to finisher at bottom via goto-free duplication:
        // (extremely unlikely path; duplicate minimal finisher)
    } else {
        // ================= pure stream block =================
        int bp = blk - BB;            // row id 0..2047
        int b  = bp >> 6;

        // ------- rowsum: 4 accumulators, unroll 8, __ldcs (R12) -------
        const float4* row4 = (const float4*)(outputs + (size_t)bp * VV);
        float a0 = 0.0f, a1 = 0.0f, a2 = 0.0f, a3 = 0.0f;
        {
            int idx = tid;
            #pragma unroll 8
            for (int k = 0; k < 31; k++, idx += 256) {      // 31*256 = 7936
                float4 v = __ldcs(row4 + idx);
                float s = (v.x + v.y) + (v.z + v.w);
                switch (k & 3) {
                    case 0: a0 += s; break;
                    case 1: a1 += s; break;
                    case 2: a2 += s; break;
                    default: a3 += s; break;
                }
            }
            if (tid < (VV / 4 - 7936)) {                    // tail: 64 float4
                float4 v = __ldcs(row4 + 7936 + tid);
                a0 += (v.x + v.y) + (v.z + v.w);
            }
        }
        float acc = (a0 + a1) + (a2 + a3);
        #pragma unroll
        for (int off = 16; off; off >>= 1)
            acc += __shfl_down_sync(FULL, acc, off);
        __shared__ float sred[8];
        if (lane == 0) sred[wid] = acc;

        // ---------------- wait for this batch's DP mask --------------
        if (tid == 0) {
            while (atomicAdd(&g_flag[b], 0) == 0) __nanosleep(64);
        }
        __syncthreads();
        __threadfence();

        // ---------------- dedup gather of distinct argmin symbols ----
        __shared__ int stg[LL];
        __shared__ unsigned char str[LL];
        if (tid < LL) {
            stg[tid] = targets[b * LL + tid];
            uint2 m = g_mask[bp];
            str[tid] = (unsigned char)((((tid & 1) ? m.y : m.x) >> (tid >> 1)) & 1);
        }
        __syncthreads();

        float contrib = 0.0f, cm = 0.0f;
        if (tid < LL && str[tid]) {
            int tv = stg[tid];
            bool first = true;
            for (int k = 0; k < tid; k++)
                if (str[k] && stg[k] == tv) { first = false; break; }
            if (first) {
                contrib = outputs[(size_t)bp * VV + tv];   // L2-hot
                cm = 1.0f;
            }
        }
        #pragma unroll
        for (int off = 16; off; off >>= 1) {
            contrib += __shfl_down_sync(FULL, contrib, off);
            cm      += __shfl_down_sync(FULL, cm, off);
        }
        __shared__ float sc2[2], sm2[2];
        if (tid < LL && lane == 0) { sc2[wid] = contrib; sm2[wid] = cm; }
        __syncthreads();

        if (tid == 0) {
            float s = 0.0f;
            #pragma unroll
            for (int w = 0; w < 8; w++) s += sred[w];
            g_sum[bp] = s;
            g_S[bp]   = sc2[0] + sc2[1];
            g_m[bp]   = (int)(sm2[0] + sm2[1]);
        }

        __shared__ int s_last;
        if (tid == 0) {
            __threadfence();
            unsigned prev = atomicAdd(&g_done, 1u);
            s_last = (prev == (unsigned)(NBLK - 1));
        }
        __syncthreads();
        if (!s_last) return;
    }

    // ---------------- last-block finisher (all fp32) ----------------
    // thread t = bb*8 + s : batch bb, rows i = s + 8*k (k<8). Deterministic.
    {
        const float E1f  = 2.71828182845904523f;
        const float EM1V = 1.71828182845904523f / 32000.0f;
        const float LNV  = 10.37349118f;                 // ln(32000)
        int bb = tid >> 3, sl = tid & 7;

        float kacc = 0.0f, cnt = 0.0f;
        #pragma unroll
        for (int k = 0; k < 8; k++) {
            int i = sl + 8 * k;
            int r = bb * PP + i;
            if (mask[bb * LL + i]) {
                float mm  = (float)g_m[r];
                float D   = ((float)VV - mm) + mm * E1f;
                float p0  = 1.0f / D;
                float p1  = E1f * p0;
                float x   = mm * EM1V;
                float l1p = x * (1.0f + x * (-0.5f + x * (0.33333333f + x * -0.25f)));
                float lnD = LNV + l1p;
                kacc += mm * p1 * (1.0f - lnD) - ((float)VV - mm) * p0 * lnD
                      - p0 * g_sum[r] - (p1 - p0) * g_S[r];
                cnt  += 1.0f;
            }
        }
        __shared__ float spart[256], scnt[256];
        spart[tid] = kacc; scnt[tid] = cnt;
        __syncthreads();

        if (tid < BB) {
            float s = 0.0f, w = 0.0f;
            #pragma unroll
            for (int k = 0; k < 8; k++) { s += spart[tid * 8 + k]; w += scnt[tid * 8 + k]; }
            float pb = s / (w + 1e-13f);
            float ne = (w > 0.0f) ? 1.0f : 0.0f;
            #pragma unroll
            for (int off = 16; off; off >>= 1) {
                pb += __shfl_down_sync(FULL, pb, off);
                ne += __shfl_down_sync(FULL, ne, off);
            }
            if (tid == 0) out[0] = pb / (ne + 1e-13f);
            g_flag[tid] = 0;                   // reset handshake for next replay
            if (tid == 0) g_done = 0u;
        }
    }
}

// ---------------------------------------------------------------------------
extern "C" void kernel_launch(void* const* d_in, const int* in_sizes, int n_in,
                              void* d_out, int out_size) {
    const float*         outputs = (const float*)d_in[0];
    const int*           syms    = (const int*)d_in[1];
    const int*           targets = (const int*)d_in[2];
    const unsigned char* mask    = (const unsigned char*)d_in[3];

    k_main<<<NBLK, 256>>>(outputs, syms, targets, mask, (float*)d_out);
}